// round 1
// baseline (speedup 1.0000x reference)
#include <cuda_runtime.h>
#include <math.h>

#define NB   2048
#define DIMT 480
#define HID  1024
#define ZD   256
#define K0   16384
#define K1   4096
#define K2   1024

// ---------------- scratch (device globals; no allocations allowed) ----------------
constexpr long SZ_P0  = (long)NB * K0;
constexpr long SZ_P1  = (long)NB * K1;
constexpr long SZ_P2  = (long)NB * K2;
constexpr long SZ_H   = (long)NB * HID;
constexpr long SZ_Z   = (long)NB * ZD;

constexpr long OFF_P0   = 0;
constexpr long OFF_P1   = OFF_P0 + SZ_P0;
constexpr long OFF_P2   = OFF_P1 + SZ_P1;
constexpr long OFF_E    = OFF_P2 + SZ_P2;
constexpr long OFF_A1   = OFF_E  + SZ_H;
constexpr long OFF_XH1  = OFF_A1 + SZ_H;
constexpr long OFF_H1   = OFF_XH1 + SZ_H;
constexpr long OFF_A2   = OFF_H1 + SZ_H;
constexpr long OFF_XH2  = OFF_A2 + SZ_Z;
constexpr long OFF_DA2  = OFF_XH2 + SZ_Z;
constexpr long OFF_DH1  = OFF_DA2 + SZ_Z;
constexpr long OFF_DA1  = OFF_DH1 + SZ_H;
constexpr long OFF_DE   = OFF_DA1 + SZ_H;
constexpr long OFF_RS1  = OFF_DE  + SZ_H;
constexpr long OFF_RS2  = OFF_RS1 + NB;
constexpr long SZ_TOTAL = OFF_RS2 + NB;

__device__ float g_scratch[SZ_TOTAL];

// ---------------- SGEMM: C = alpha*A@B(^T) + beta*C + bias ----------------
// A: MxK row-major.  NT=false: B is KxN row-major.  NT=true: B is NxK row-major (B^T).
template<bool NT>
__global__ __launch_bounds__(256) void sgemm(
    const float* __restrict__ A, const float* __restrict__ B, float* __restrict__ C,
    int M, int Nn, int K, float alpha, float beta, const float* __restrict__ bias)
{
    __shared__ float As[16][132];
    __shared__ float Bs[16][132];
    int tid = threadIdx.x;
    int bm = blockIdx.y * 128, bn = blockIdx.x * 128;
    int tx = tid & 15, ty = tid >> 4;
    float acc[8][8];
    #pragma unroll
    for (int i = 0; i < 8; i++)
        #pragma unroll
        for (int j = 0; j < 8; j++) acc[i][j] = 0.f;

    for (int kt = 0; kt < K; kt += 16) {
        #pragma unroll
        for (int i = 0; i < 2; i++) {
            int idx = tid + i * 256;          // 0..511
            int row = idx >> 2;               // 0..127 (m within tile)
            int k4  = (idx & 3) << 2;         // 0,4,8,12
            float4 v = *(const float4*)(A + (long)(bm + row) * K + kt + k4);
            As[k4+0][row] = v.x; As[k4+1][row] = v.y;
            As[k4+2][row] = v.z; As[k4+3][row] = v.w;
        }
        if (NT) {
            #pragma unroll
            for (int i = 0; i < 2; i++) {
                int idx = tid + i * 256;
                int row = idx >> 2;           // n within tile
                int k4  = (idx & 3) << 2;
                float4 v = *(const float4*)(B + (long)(bn + row) * K + kt + k4);
                Bs[k4+0][row] = v.x; Bs[k4+1][row] = v.y;
                Bs[k4+2][row] = v.z; Bs[k4+3][row] = v.w;
            }
        } else {
            #pragma unroll
            for (int i = 0; i < 2; i++) {
                int idx = tid + i * 256;
                int krow = idx >> 5;          // 0..15
                int n4   = (idx & 31) << 2;   // 0..124
                float4 v = *(const float4*)(B + (long)(kt + krow) * Nn + bn + n4);
                *(float4*)&Bs[krow][n4] = v;
            }
        }
        __syncthreads();
        #pragma unroll
        for (int kk = 0; kk < 16; kk++) {
            float a[8], b[8];
            *(float4*)(a)     = *(const float4*)&As[kk][ty * 8];
            *(float4*)(a + 4) = *(const float4*)&As[kk][ty * 8 + 4];
            *(float4*)(b)     = *(const float4*)&Bs[kk][tx * 8];
            *(float4*)(b + 4) = *(const float4*)&Bs[kk][tx * 8 + 4];
            #pragma unroll
            for (int i = 0; i < 8; i++)
                #pragma unroll
                for (int j = 0; j < 8; j++)
                    acc[i][j] += a[i] * b[j];
        }
        __syncthreads();
    }
    #pragma unroll
    for (int i = 0; i < 8; i++) {
        int m = bm + ty * 8 + i;
        float* Crow = C + (long)m * Nn + bn + tx * 8;
        #pragma unroll
        for (int j = 0; j < 8; j++) {
            float v = alpha * acc[i][j];
            if (beta != 0.f) v += beta * Crow[j];
            if (bias) v += bias[bn + tx * 8 + j];
            Crow[j] = v;
        }
    }
}

// ---------------- build pairwise product matrices ----------------
__global__ void build_P0(const float* __restrict__ t, float* __restrict__ P) {
    int idx = blockIdx.x * 256 + threadIdx.x;     // NB*K0 total
    int b = idx >> 14;
    int uv = idx & (K0 - 1);
    int u = uv >> 7, v = uv & 127;
    const float* r = t + (long)b * DIMT;
    P[idx] = r[u] * r[v];
}
__global__ void build_P1(const float* __restrict__ t, float* __restrict__ P) {
    int idx = blockIdx.x * 256 + threadIdx.x;     // NB*K1
    int b = idx >> 12;
    int uv = idx & (K1 - 1);
    int u = uv >> 6, v = uv & 63;
    const float* r = t + (long)b * DIMT + 128;
    float s = 0.f;
    #pragma unroll
    for (int m = 0; m < 3; m++) s += r[u * 3 + m] * r[v * 3 + m];
    P[idx] = s;
}
__global__ void build_P2(const float* __restrict__ t, float* __restrict__ P) {
    int idx = blockIdx.x * 256 + threadIdx.x;     // NB*K2
    int b = idx >> 10;
    int uv = idx & (K2 - 1);
    int u = uv >> 5, v = uv & 31;
    const float* r = t + (long)b * DIMT + 320;
    float s = 0.f;
    #pragma unroll
    for (int m = 0; m < 5; m++) s += r[u * 5 + m] * r[v * 5 + m];
    P[idx] = s;
}

// ---------------- block reduce ----------------
__device__ __forceinline__ float blockReduceSum(float val) {
    __shared__ float sh[8];
    int lane = threadIdx.x & 31, w = threadIdx.x >> 5;
    #pragma unroll
    for (int o = 16; o > 0; o >>= 1) val += __shfl_down_sync(0xffffffffu, val, o);
    __syncthreads();
    if (lane == 0) sh[w] = val;
    __syncthreads();
    float r = 0.f;
    if (threadIdx.x == 0) {
        int nw = blockDim.x >> 5;
        for (int i = 0; i < nw; i++) r += sh[i];
    }
    return r;  // valid on thread 0 only
}

// ---------------- LayerNorm + SiLU forward (per row) ----------------
template<int PER>
__global__ __launch_bounds__(256) void ln_silu_fwd(
    const float* __restrict__ a, const float* __restrict__ gam, const float* __restrict__ bet,
    float* __restrict__ xh, float* __restrict__ rstd, float* __restrict__ h)
{
    const int D = PER * 256;
    int b = blockIdx.x, tid = threadIdx.x;
    const float* row = a + (long)b * D;
    float v[PER];
    float s = 0.f;
    #pragma unroll
    for (int i = 0; i < PER; i++) { v[i] = row[tid + (i << 8)]; s += v[i]; }
    s = blockReduceSum(s);
    __shared__ float bc;
    if (tid == 0) bc = s * (1.f / D);
    __syncthreads();
    float mu = bc;
    float q = 0.f;
    #pragma unroll
    for (int i = 0; i < PER; i++) { float d = v[i] - mu; q += d * d; }
    q = blockReduceSum(q);
    if (tid == 0) { float r = rsqrtf(q * (1.f / D) + 1e-6f); bc = r; rstd[b] = r; }
    __syncthreads();
    float r = bc;
    #pragma unroll
    for (int i = 0; i < PER; i++) {
        int c = tid + (i << 8);
        float x = (v[i] - mu) * r;
        xh[(long)b * D + c] = x;
        float z = x * gam[c] + bet[c];
        float sg = 1.f / (1.f + expf(-z));
        h[(long)b * D + c] = z * sg;
    }
}

// ---------------- (SiLU + LN) backward (per row) ----------------
// dh==nullptr means upstream cotangent of ones.
template<int PER>
__global__ __launch_bounds__(256) void ln_silu_bwd(
    const float* __restrict__ dh, const float* __restrict__ xhv_, const float* __restrict__ rstd,
    const float* __restrict__ gam, const float* __restrict__ bet, float* __restrict__ da)
{
    const int D = PER * 256;
    int b = blockIdx.x, tid = threadIdx.x;
    float xh[PER], dxh[PER];
    float s1 = 0.f, s2 = 0.f;
    #pragma unroll
    for (int i = 0; i < PER; i++) {
        int c = tid + (i << 8);
        float x = xhv_[(long)b * D + c];
        float z = x * gam[c] + bet[c];
        float sg = 1.f / (1.f + expf(-z));
        float ds = sg * (1.f + z * (1.f - sg));        // silu'(z)
        float up = dh ? dh[(long)b * D + c] : 1.f;
        float dx = up * ds * gam[c];                   // d wrt xhat
        xh[i] = x; dxh[i] = dx;
        s1 += dx; s2 += dx * x;
    }
    __shared__ float m1s, m2s;
    float t1 = blockReduceSum(s1);
    if (tid == 0) m1s = t1 * (1.f / D);
    float t2 = blockReduceSum(s2);
    if (tid == 0) m2s = t2 * (1.f / D);
    __syncthreads();
    float m1 = m1s, m2 = m2s, r = rstd[b];
    #pragma unroll
    for (int i = 0; i < PER; i++) {
        int c = tid + (i << 8);
        da[(long)b * D + c] = r * (dxh[i] - m1 - xh[i] * m2);
    }
}

// ---------------- quadratic-form gradients -> y ----------------
__global__ __launch_bounds__(128) void grad0(const float* __restrict__ dP,
                                             const float* __restrict__ t, float* __restrict__ y)
{
    __shared__ float Ts[64][129];
    __shared__ float xs[128];
    int b = blockIdx.x, tid = threadIdx.x;
    xs[tid] = t[(long)b * DIMT + tid];
    float racc = 0.f, cacc = 0.f;
    for (int ch = 0; ch < 2; ch++) {
        __syncthreads();
        const float* P = dP + (long)b * K0 + ch * 64 * 128;
        for (int i = tid; i < 2048; i += 128) {       // 2048 float4 = 64x128
            float4 v = *(const float4*)(P + i * 4);
            int r = (i * 4) >> 7, c = (i * 4) & 127;
            Ts[r][c] = v.x; Ts[r][c + 1] = v.y; Ts[r][c + 2] = v.z; Ts[r][c + 3] = v.w;
        }
        __syncthreads();
        int u = tid;
        if ((u >> 6) == ch) {
            int ul = u & 63;
            float s = 0.f;
            #pragma unroll 8
            for (int v = 0; v < 128; v++) s += Ts[ul][v] * xs[v];
            racc = s;
        }
        float s = 0.f;
        #pragma unroll 8
        for (int up = 0; up < 64; up++) s += Ts[up][u] * xs[ch * 64 + up];
        cacc += s;
    }
    y[(long)b * DIMT + tid] = racc + cacc;
}

__global__ __launch_bounds__(192) void grad1(const float* __restrict__ dP,
                                             const float* __restrict__ t, float* __restrict__ y)
{
    __shared__ float Ts[64][65];
    __shared__ float xs[192];
    int b = blockIdx.x, tid = threadIdx.x;
    const float* P = dP + (long)b * K1;
    for (int i = tid; i < 4096; i += 192) Ts[i >> 6][i & 63] = P[i];
    xs[tid] = t[(long)b * DIMT + 128 + tid];
    __syncthreads();
    int u = tid / 3, m = tid - u * 3;
    float s = 0.f;
    #pragma unroll 8
    for (int v = 0; v < 64; v++) s += (Ts[u][v] + Ts[v][u]) * xs[v * 3 + m];
    y[(long)b * DIMT + 128 + tid] = s;
}

__global__ __launch_bounds__(160) void grad2(const float* __restrict__ dP,
                                             const float* __restrict__ t, float* __restrict__ y)
{
    __shared__ float Ts[32][33];
    __shared__ float xs[160];
    int b = blockIdx.x, tid = threadIdx.x;
    const float* P = dP + (long)b * K2;
    for (int i = tid; i < 1024; i += 160) Ts[i >> 5][i & 31] = P[i];
    xs[tid] = t[(long)b * DIMT + 320 + tid];
    __syncthreads();
    int u = tid / 5, m = tid - u * 5;
    float s = 0.f;
    #pragma unroll 8
    for (int v = 0; v < 32; v++) s += (Ts[u][v] + Ts[v][u]) * xs[v * 5 + m];
    y[(long)b * DIMT + 320 + tid] = s;
}

// ---------------- launch ----------------
extern "C" void kernel_launch(void* const* d_in, const int* in_sizes, int n_in,
                              void* d_out, int out_size)
{
    const float* tin = (const float*)d_in[0];
    const float* w0  = (const float*)d_in[1];   // (128,128,HID) -> flat (K0, HID)
    const float* w1  = (const float*)d_in[2];   // (64,64,HID)   -> flat (K1, HID)
    const float* w2  = (const float*)d_in[3];   // (32,32,HID)   -> flat (K2, HID)
    const float* W1  = (const float*)d_in[4];   // (HID, HID)
    const float* b1  = (const float*)d_in[5];
    const float* g1  = (const float*)d_in[6];
    const float* be1 = (const float*)d_in[7];
    const float* W2  = (const float*)d_in[8];   // (HID, ZD)
    const float* b2  = (const float*)d_in[9];
    const float* g2  = (const float*)d_in[10];
    const float* be2 = (const float*)d_in[11];

    float* out  = (float*)d_out;
    float* xout = out;                          // (NB, ZD)
    float* yout = out + (long)NB * ZD;          // (NB, DIMT)

    float* base = nullptr;
    cudaGetSymbolAddress((void**)&base, g_scratch);
    float* P0  = base + OFF_P0;
    float* P1  = base + OFF_P1;
    float* P2  = base + OFF_P2;
    float* e   = base + OFF_E;
    float* a1  = base + OFF_A1;
    float* xh1 = base + OFF_XH1;
    float* h1  = base + OFF_H1;
    float* a2  = base + OFF_A2;
    float* xh2 = base + OFF_XH2;
    float* da2 = base + OFF_DA2;
    float* dh1 = base + OFF_DH1;
    float* da1 = base + OFF_DA1;
    float* de  = base + OFF_DE;
    float* rs1 = base + OFF_RS1;
    float* rs2 = base + OFF_RS2;

    const float s0 = 1.0f / sqrtf(21504.0f);
    const float s1 = s0 / sqrtf(3.0f);
    const float s2 = s0 / sqrtf(5.0f);

    // ---- forward ----
    build_P0<<<(NB * K0) / 256, 256>>>(tin, P0);
    build_P1<<<(NB * K1) / 256, 256>>>(tin, P1);
    build_P2<<<(NB * K2) / 256, 256>>>(tin, P2);

    dim3 gE(HID / 128, NB / 128);
    sgemm<false><<<gE, 256>>>(P0, w0, e, NB, HID, K0, s0, 0.f, nullptr);
    sgemm<false><<<gE, 256>>>(P1, w1, e, NB, HID, K1, s1, 1.f, nullptr);
    sgemm<false><<<gE, 256>>>(P2, w2, e, NB, HID, K2, s2, 1.f, nullptr);

    sgemm<false><<<dim3(HID / 128, NB / 128), 256>>>(e, W1, a1, NB, HID, HID, 1.f, 0.f, b1);
    ln_silu_fwd<4><<<NB, 256>>>(a1, g1, be1, xh1, rs1, h1);
    sgemm<false><<<dim3(ZD / 128, NB / 128), 256>>>(h1, W2, a2, NB, ZD, HID, 1.f, 0.f, b2);
    ln_silu_fwd<1><<<NB, 256>>>(a2, g2, be2, xh2, rs2, xout);

    // ---- backward ----
    ln_silu_bwd<1><<<NB, 256>>>(nullptr, xh2, rs2, g2, be2, da2);
    sgemm<true><<<dim3(HID / 128, NB / 128), 256>>>(da2, W2, dh1, NB, HID, ZD, 1.f, 0.f, nullptr);
    ln_silu_bwd<4><<<NB, 256>>>(dh1, xh1, rs1, g1, be1, da1);
    sgemm<true><<<dim3(HID / 128, NB / 128), 256>>>(da1, W1, de, NB, HID, HID, 1.f, 0.f, nullptr);

    sgemm<true><<<dim3(K0 / 128, NB / 128), 256>>>(de, w0, P0, NB, K0, HID, s0, 0.f, nullptr);
    sgemm<true><<<dim3(K1 / 128, NB / 128), 256>>>(de, w1, P1, NB, K1, HID, s1, 0.f, nullptr);
    sgemm<true><<<dim3(K2 / 128, NB / 128), 256>>>(de, w2, P2, NB, K2, HID, s2, 0.f, nullptr);

    grad0<<<NB, 128>>>(P0, tin, yout);
    grad1<<<NB, 192>>>(P1, tin, yout);
    grad2<<<NB, 160>>>(P2, tin, yout);
}

// round 2
// speedup vs baseline: 1.0029x; 1.0029x over previous
#include <cuda_runtime.h>
#include <math.h>

#define NB   2048
#define DIMT 480
#define HID  1024
#define ZD   256
#define K0   16384
#define K1   4096
#define K2   1024

// ---------------- scratch (device globals; no allocations allowed) ----------------
constexpr long SZ_P0  = (long)NB * K0;
constexpr long SZ_P1  = (long)NB * K1;
constexpr long SZ_P2  = (long)NB * K2;
constexpr long SZ_H   = (long)NB * HID;
constexpr long SZ_Z   = (long)NB * ZD;

constexpr long OFF_P0   = 0;
constexpr long OFF_P1   = OFF_P0 + SZ_P0;
constexpr long OFF_P2   = OFF_P1 + SZ_P1;
constexpr long OFF_E    = OFF_P2 + SZ_P2;
constexpr long OFF_A1   = OFF_E  + SZ_H;
constexpr long OFF_XH1  = OFF_A1 + SZ_H;
constexpr long OFF_H1   = OFF_XH1 + SZ_H;
constexpr long OFF_A2   = OFF_H1 + SZ_H;
constexpr long OFF_XH2  = OFF_A2 + SZ_Z;
constexpr long OFF_DA2  = OFF_XH2 + SZ_Z;
constexpr long OFF_DH1  = OFF_DA2 + SZ_Z;
constexpr long OFF_DA1  = OFF_DH1 + SZ_H;
constexpr long OFF_DE   = OFF_DA1 + SZ_H;
constexpr long OFF_RS1  = OFF_DE  + SZ_H;
constexpr long OFF_RS2  = OFF_RS1 + NB;
constexpr long SZ_TOTAL = OFF_RS2 + NB;

__device__ float g_scratch[SZ_TOTAL];

// ---------------- SGEMM: C = alpha*A@B(^T) + beta*C + bias ----------------
// A: MxK row-major.  NT=false: B is KxN row-major.  NT=true: B is NxK row-major (B^T).
template<bool NT>
__global__ __launch_bounds__(256) void sgemm(
    const float* __restrict__ A, const float* __restrict__ B, float* __restrict__ C,
    int M, int Nn, int K, float alpha, float beta, const float* __restrict__ bias)
{
    __shared__ float As[16][132];
    __shared__ float Bs[16][132];
    int tid = threadIdx.x;
    int bm = blockIdx.y * 128, bn = blockIdx.x * 128;
    int tx = tid & 15, ty = tid >> 4;
    float acc[8][8];
    #pragma unroll
    for (int i = 0; i < 8; i++)
        #pragma unroll
        for (int j = 0; j < 8; j++) acc[i][j] = 0.f;

    for (int kt = 0; kt < K; kt += 16) {
        #pragma unroll
        for (int i = 0; i < 2; i++) {
            int idx = tid + i * 256;          // 0..511
            int row = idx >> 2;               // 0..127 (m within tile)
            int k4  = (idx & 3) << 2;         // 0,4,8,12
            float4 v = *(const float4*)(A + (long)(bm + row) * K + kt + k4);
            As[k4+0][row] = v.x; As[k4+1][row] = v.y;
            As[k4+2][row] = v.z; As[k4+3][row] = v.w;
        }
        if (NT) {
            #pragma unroll
            for (int i = 0; i < 2; i++) {
                int idx = tid + i * 256;
                int row = idx >> 2;           // n within tile
                int k4  = (idx & 3) << 2;
                float4 v = *(const float4*)(B + (long)(bn + row) * K + kt + k4);
                Bs[k4+0][row] = v.x; Bs[k4+1][row] = v.y;
                Bs[k4+2][row] = v.z; Bs[k4+3][row] = v.w;
            }
        } else {
            #pragma unroll
            for (int i = 0; i < 2; i++) {
                int idx = tid + i * 256;
                int krow = idx >> 5;          // 0..15
                int n4   = (idx & 31) << 2;   // 0..124
                float4 v = *(const float4*)(B + (long)(kt + krow) * Nn + bn + n4);
                *(float4*)&Bs[krow][n4] = v;
            }
        }
        __syncthreads();
        #pragma unroll
        for (int kk = 0; kk < 16; kk++) {
            float a[8], b[8];
            *(float4*)(a)     = *(const float4*)&As[kk][ty * 8];
            *(float4*)(a + 4) = *(const float4*)&As[kk][ty * 8 + 4];
            *(float4*)(b)     = *(const float4*)&Bs[kk][tx * 8];
            *(float4*)(b + 4) = *(const float4*)&Bs[kk][tx * 8 + 4];
            #pragma unroll
            for (int i = 0; i < 8; i++)
                #pragma unroll
                for (int j = 0; j < 8; j++)
                    acc[i][j] += a[i] * b[j];
        }
        __syncthreads();
    }
    #pragma unroll
    for (int i = 0; i < 8; i++) {
        int m = bm + ty * 8 + i;
        float* Crow = C + (long)m * Nn + bn + tx * 8;
        #pragma unroll
        for (int j = 0; j < 8; j++) {
            float v = alpha * acc[i][j];
            if (beta != 0.f) v += beta * Crow[j];
            if (bias) v += bias[bn + tx * 8 + j];
            Crow[j] = v;
        }
    }
}

// ---------------- build pairwise product matrices ----------------
__global__ void build_P0(const float* __restrict__ t, float* __restrict__ P) {
    int idx = blockIdx.x * 256 + threadIdx.x;     // NB*K0 total
    int b = idx >> 14;
    int uv = idx & (K0 - 1);
    int u = uv >> 7, v = uv & 127;
    const float* r = t + (long)b * DIMT;
    P[idx] = r[u] * r[v];
}
__global__ void build_P1(const float* __restrict__ t, float* __restrict__ P) {
    int idx = blockIdx.x * 256 + threadIdx.x;     // NB*K1
    int b = idx >> 12;
    int uv = idx & (K1 - 1);
    int u = uv >> 6, v = uv & 63;
    const float* r = t + (long)b * DIMT + 128;
    float s = 0.f;
    #pragma unroll
    for (int m = 0; m < 3; m++) s += r[u * 3 + m] * r[v * 3 + m];
    P[idx] = s;
}
__global__ void build_P2(const float* __restrict__ t, float* __restrict__ P) {
    int idx = blockIdx.x * 256 + threadIdx.x;     // NB*K2
    int b = idx >> 10;
    int uv = idx & (K2 - 1);
    int u = uv >> 5, v = uv & 31;
    const float* r = t + (long)b * DIMT + 320;
    float s = 0.f;
    #pragma unroll
    for (int m = 0; m < 5; m++) s += r[u * 5 + m] * r[v * 5 + m];
    P[idx] = s;
}

// ---------------- block reduce ----------------
__device__ __forceinline__ float blockReduceSum(float val) {
    __shared__ float sh[8];
    int lane = threadIdx.x & 31, w = threadIdx.x >> 5;
    #pragma unroll
    for (int o = 16; o > 0; o >>= 1) val += __shfl_down_sync(0xffffffffu, val, o);
    __syncthreads();
    if (lane == 0) sh[w] = val;
    __syncthreads();
    float r = 0.f;
    if (threadIdx.x == 0) {
        int nw = blockDim.x >> 5;
        for (int i = 0; i < nw; i++) r += sh[i];
    }
    return r;  // valid on thread 0 only
}

// ---------------- LayerNorm + SiLU forward (per row) ----------------
template<int PER>
__global__ __launch_bounds__(256) void ln_silu_fwd(
    const float* __restrict__ a, const float* __restrict__ gam, const float* __restrict__ bet,
    float* __restrict__ xh, float* __restrict__ rstd, float* __restrict__ h)
{
    const int D = PER * 256;
    int b = blockIdx.x, tid = threadIdx.x;
    const float* row = a + (long)b * D;
    float v[PER];
    float s = 0.f;
    #pragma unroll
    for (int i = 0; i < PER; i++) { v[i] = row[tid + (i << 8)]; s += v[i]; }
    s = blockReduceSum(s);
    __shared__ float bc;
    if (tid == 0) bc = s * (1.f / D);
    __syncthreads();
    float mu = bc;
    float q = 0.f;
    #pragma unroll
    for (int i = 0; i < PER; i++) { float d = v[i] - mu; q += d * d; }
    q = blockReduceSum(q);
    if (tid == 0) { float r = rsqrtf(q * (1.f / D) + 1e-6f); bc = r; rstd[b] = r; }
    __syncthreads();
    float r = bc;
    #pragma unroll
    for (int i = 0; i < PER; i++) {
        int c = tid + (i << 8);
        float x = (v[i] - mu) * r;
        xh[(long)b * D + c] = x;
        float z = x * gam[c] + bet[c];
        float sg = 1.f / (1.f + expf(-z));
        h[(long)b * D + c] = z * sg;
    }
}

// ---------------- (SiLU + LN) backward (per row) ----------------
// dh==nullptr means upstream cotangent of ones.
template<int PER>
__global__ __launch_bounds__(256) void ln_silu_bwd(
    const float* __restrict__ dh, const float* __restrict__ xhv_, const float* __restrict__ rstd,
    const float* __restrict__ gam, const float* __restrict__ bet, float* __restrict__ da)
{
    const int D = PER * 256;
    int b = blockIdx.x, tid = threadIdx.x;
    float xh[PER], dxh[PER];
    float s1 = 0.f, s2 = 0.f;
    #pragma unroll
    for (int i = 0; i < PER; i++) {
        int c = tid + (i << 8);
        float x = xhv_[(long)b * D + c];
        float z = x * gam[c] + bet[c];
        float sg = 1.f / (1.f + expf(-z));
        float ds = sg * (1.f + z * (1.f - sg));        // silu'(z)
        float up = dh ? dh[(long)b * D + c] : 1.f;
        float dx = up * ds * gam[c];                   // d wrt xhat
        xh[i] = x; dxh[i] = dx;
        s1 += dx; s2 += dx * x;
    }
    __shared__ float m1s, m2s;
    float t1 = blockReduceSum(s1);
    if (tid == 0) m1s = t1 * (1.f / D);
    float t2 = blockReduceSum(s2);
    if (tid == 0) m2s = t2 * (1.f / D);
    __syncthreads();
    float m1 = m1s, m2 = m2s, r = rstd[b];
    #pragma unroll
    for (int i = 0; i < PER; i++) {
        int c = tid + (i << 8);
        da[(long)b * D + c] = r * (dxh[i] - m1 - xh[i] * m2);
    }
}

// ---------------- quadratic-form gradients -> y ----------------
__global__ __launch_bounds__(128) void grad0(const float* __restrict__ dP,
                                             const float* __restrict__ t, float* __restrict__ y)
{
    __shared__ float Ts[64][129];
    __shared__ float xs[128];
    int b = blockIdx.x, tid = threadIdx.x;
    xs[tid] = t[(long)b * DIMT + tid];
    float racc = 0.f, cacc = 0.f;
    for (int ch = 0; ch < 2; ch++) {
        __syncthreads();
        const float* P = dP + (long)b * K0 + ch * 64 * 128;
        for (int i = tid; i < 2048; i += 128) {       // 2048 float4 = 64x128
            float4 v = *(const float4*)(P + i * 4);
            int r = (i * 4) >> 7, c = (i * 4) & 127;
            Ts[r][c] = v.x; Ts[r][c + 1] = v.y; Ts[r][c + 2] = v.z; Ts[r][c + 3] = v.w;
        }
        __syncthreads();
        int u = tid;
        if ((u >> 6) == ch) {
            int ul = u & 63;
            float s = 0.f;
            #pragma unroll 8
            for (int v = 0; v < 128; v++) s += Ts[ul][v] * xs[v];
            racc = s;
        }
        float s = 0.f;
        #pragma unroll 8
        for (int up = 0; up < 64; up++) s += Ts[up][u] * xs[ch * 64 + up];
        cacc += s;
    }
    y[(long)b * DIMT + tid] = racc + cacc;
}

__global__ __launch_bounds__(192) void grad1(const float* __restrict__ dP,
                                             const float* __restrict__ t, float* __restrict__ y)
{
    __shared__ float Ts[64][65];
    __shared__ float xs[192];
    int b = blockIdx.x, tid = threadIdx.x;
    const float* P = dP + (long)b * K1;
    for (int i = tid; i < 4096; i += 192) Ts[i >> 6][i & 63] = P[i];
    xs[tid] = t[(long)b * DIMT + 128 + tid];
    __syncthreads();
    int u = tid / 3, m = tid - u * 3;
    float s = 0.f;
    #pragma unroll 8
    for (int v = 0; v < 64; v++) s += (Ts[u][v] + Ts[v][u]) * xs[v * 3 + m];
    y[(long)b * DIMT + 128 + tid] = s;
}

__global__ __launch_bounds__(160) void grad2(const float* __restrict__ dP,
                                             const float* __restrict__ t, float* __restrict__ y)
{
    __shared__ float Ts[32][33];
    __shared__ float xs[160];
    int b = blockIdx.x, tid = threadIdx.x;
    const float* P = dP + (long)b * K2;
    for (int i = tid; i < 1024; i += 160) Ts[i >> 5][i & 31] = P[i];
    xs[tid] = t[(long)b * DIMT + 320 + tid];
    __syncthreads();
    int u = tid / 5, m = tid - u * 5;
    float s = 0.f;
    #pragma unroll 8
    for (int v = 0; v < 32; v++) s += (Ts[u][v] + Ts[v][u]) * xs[v * 5 + m];
    y[(long)b * DIMT + 320 + tid] = s;
}

// ---------------- launch ----------------
extern "C" void kernel_launch(void* const* d_in, const int* in_sizes, int n_in,
                              void* d_out, int out_size)
{
    const float* tin = (const float*)d_in[0];
    const float* w0  = (const float*)d_in[1];   // (128,128,HID) -> flat (K0, HID)
    const float* w1  = (const float*)d_in[2];   // (64,64,HID)   -> flat (K1, HID)
    const float* w2  = (const float*)d_in[3];   // (32,32,HID)   -> flat (K2, HID)
    const float* W1  = (const float*)d_in[4];   // (HID, HID)
    const float* b1  = (const float*)d_in[5];
    const float* g1  = (const float*)d_in[6];
    const float* be1 = (const float*)d_in[7];
    const float* W2  = (const float*)d_in[8];   // (HID, ZD)
    const float* b2  = (const float*)d_in[9];
    const float* g2  = (const float*)d_in[10];
    const float* be2 = (const float*)d_in[11];

    float* out  = (float*)d_out;
    float* xout = out;                          // (NB, ZD)
    float* yout = out + (long)NB * ZD;          // (NB, DIMT)

    float* base = nullptr;
    cudaGetSymbolAddress((void**)&base, g_scratch);
    float* P0  = base + OFF_P0;
    float* P1  = base + OFF_P1;
    float* P2  = base + OFF_P2;
    float* e   = base + OFF_E;
    float* a1  = base + OFF_A1;
    float* xh1 = base + OFF_XH1;
    float* h1  = base + OFF_H1;
    float* a2  = base + OFF_A2;
    float* xh2 = base + OFF_XH2;
    float* da2 = base + OFF_DA2;
    float* dh1 = base + OFF_DH1;
    float* da1 = base + OFF_DA1;
    float* de  = base + OFF_DE;
    float* rs1 = base + OFF_RS1;
    float* rs2 = base + OFF_RS2;

    const float s0 = 1.0f / sqrtf(21504.0f);
    const float s1 = s0 / sqrtf(3.0f);
    const float s2 = s0 / sqrtf(5.0f);

    // ---- forward ----
    build_P0<<<(NB * K0) / 256, 256>>>(tin, P0);
    build_P1<<<(NB * K1) / 256, 256>>>(tin, P1);
    build_P2<<<(NB * K2) / 256, 256>>>(tin, P2);

    dim3 gE(HID / 128, NB / 128);
    sgemm<false><<<gE, 256>>>(P0, w0, e, NB, HID, K0, s0, 0.f, nullptr);
    sgemm<false><<<gE, 256>>>(P1, w1, e, NB, HID, K1, s1, 1.f, nullptr);
    sgemm<false><<<gE, 256>>>(P2, w2, e, NB, HID, K2, s2, 1.f, nullptr);

    sgemm<false><<<dim3(HID / 128, NB / 128), 256>>>(e, W1, a1, NB, HID, HID, 1.f, 0.f, b1);
    ln_silu_fwd<4><<<NB, 256>>>(a1, g1, be1, xh1, rs1, h1);
    sgemm<false><<<dim3(ZD / 128, NB / 128), 256>>>(h1, W2, a2, NB, ZD, HID, 1.f, 0.f, b2);
    ln_silu_fwd<1><<<NB, 256>>>(a2, g2, be2, xh2, rs2, xout);

    // ---- backward ----
    ln_silu_bwd<1><<<NB, 256>>>(nullptr, xh2, rs2, g2, be2, da2);
    sgemm<true><<<dim3(HID / 128, NB / 128), 256>>>(da2, W2, dh1, NB, HID, ZD, 1.f, 0.f, nullptr);
    ln_silu_bwd<4><<<NB, 256>>>(dh1, xh1, rs1, g1, be1, da1);
    sgemm<true><<<dim3(HID / 128, NB / 128), 256>>>(da1, W1, de, NB, HID, HID, 1.f, 0.f, nullptr);

    sgemm<true><<<dim3(K0 / 128, NB / 128), 256>>>(de, w0, P0, NB, K0, HID, s0, 0.f, nullptr);
    sgemm<true><<<dim3(K1 / 128, NB / 128), 256>>>(de, w1, P1, NB, K1, HID, s1, 0.f, nullptr);
    sgemm<true><<<dim3(K2 / 128, NB / 128), 256>>>(de, w2, P2, NB, K2, HID, s2, 0.f, nullptr);

    grad0<<<NB, 128>>>(P0, tin, yout);
    grad1<<<NB, 192>>>(P1, tin, yout);
    grad2<<<NB, 160>>>(P2, tin, yout);
}